// round 17
// baseline (speedup 1.0000x reference)
#include <cuda_runtime.h>
#include <cstdint>
#include <cstddef>

// ---------------------------------------------------------------------------
// RGCN (2 layers), warp-specialized fused layer kernel (round 16):
//   per CTA: 128 nodes x 128 out-cols, K=1152 (9 relation tiles of 128).
//   warps 0-7  (256 thr): MMA consumers — proven R12 m16n8k8 tf32 loop,
//                         Bs staged in 16-row double-buffered chunks.
//   warps 8-15 (256 thr): gather producers — segment-mean into double-buffered
//                         128x128 A-tiles in smem (tf32-rounded, same math as
//                         the split pipeline). feat is L2-resident.
//   handoff: named barriers (full/free per A-buffer, 512-count arrive/sync;
//            MMA-internal Bs sync with 256-count).
//   Xcat (230 MB) is GONE -> ~870 MB less DRAM traffic per run.
// CSR build + merged weight prep unchanged from R15 (proven).
// tcgen05 unavailable (harness PTX targets sm_103 without 'a').
// ---------------------------------------------------------------------------

#define NNODES 50000
#define NEDGES 1000000
#define CDIM   128
#define NREL   8
#define NRSEG  (NNODES * NREL)
#define KDIM   (CDIM * (NREL + 1))      // 1152
#define SCAN_CHUNK 1024
#define NSCAN_BLOCKS ((NRSEG + SCAN_CHUNK - 1) / SCAN_CHUNK)   // 391

// named barrier ids (0 reserved for __syncthreads)
#define BAR_FULL0 1
#define BAR_FULL1 2
#define BAR_FREE0 3
#define BAR_FREE1 4
#define BAR_MMA_A 5
#define BAR_MMA_B 6

// ---- scratch (device globals; no runtime allocation allowed) ----
__device__ int   g_deg[NRSEG];          // zero at load; re-zeroed by scan3 each call
__device__ int   g_off[NRSEG + 1];
__device__ int   g_cur[NRSEG];
__device__ int   g_bsum[512];
__device__ int   g_bscan[512];
__device__ int   g_esrc[NEDGES];
__device__ __align__(256) float g_h[(size_t)NNODES * CDIM];      // 25.6 MB
__device__ __align__(256) float g_w1[KDIM * CDIM];
__device__ __align__(256) float g_w2[KDIM * CDIM];
__device__ __align__(16)  float g_b2[CDIM];

// ---------------------------------------------------------------------------
// helpers
// ---------------------------------------------------------------------------
__device__ __forceinline__ float tf32rf(float x) {
    uint32_t u;
    asm("cvt.rna.tf32.f32 %0, %1;" : "=r"(u) : "f"(x));
    return __uint_as_float(u);
}

__device__ __forceinline__ void cpa16(void* smem, const void* gmem, bool pred) {
    uint32_t s = (uint32_t)__cvta_generic_to_shared(smem);
    int sz = pred ? 16 : 0;
    asm volatile("cp.async.cg.shared.global [%0], [%1], 16, %2;\n"
                 :: "r"(s), "l"(gmem), "r"(sz));
}

__device__ __forceinline__ void mma8(float* c, const uint32_t* a, const uint32_t* b) {
    asm volatile(
        "mma.sync.aligned.m16n8k8.row.col.f32.tf32.tf32.f32 "
        "{%0,%1,%2,%3}, {%4,%5,%6,%7}, {%8,%9}, {%0,%1,%2,%3};"
        : "+f"(c[0]), "+f"(c[1]), "+f"(c[2]), "+f"(c[3])
        : "r"(a[0]), "r"(a[1]), "r"(a[2]), "r"(a[3]), "r"(b[0]), "r"(b[1]));
}

__device__ __forceinline__ void bar_sync(int id, int cnt) {
    asm volatile("bar.sync %0, %1;" :: "r"(id), "r"(cnt) : "memory");
}
__device__ __forceinline__ void bar_arrive(int id, int cnt) {
    asm volatile("bar.arrive %0, %1;" :: "r"(id), "r"(cnt) : "memory");
}

// ---------------------------------------------------------------------------
// CSR build (R12/R15 proven)
// ---------------------------------------------------------------------------
__global__ void hist_kernel(const int* __restrict__ dst, const int* __restrict__ et) {
    int e = blockIdx.x * blockDim.x + threadIdx.x;
    if (e >= NEDGES) return;
    atomicAdd(&g_deg[dst[e] * NREL + et[e]], 1);
}

__global__ void scan1_kernel() {
    __shared__ int sh[256];
    int t = threadIdx.x;
    int base = blockIdx.x * SCAN_CHUNK + t * 4;
    int v[4];
    int s = 0;
#pragma unroll
    for (int j = 0; j < 4; j++) {
        int idx = base + j;
        v[j] = (idx < NRSEG) ? g_deg[idx] : 0;
        s += v[j];
    }
    sh[t] = s;
    __syncthreads();
    for (int off = 1; off < 256; off <<= 1) {
        int x = (t >= off) ? sh[t - off] : 0;
        __syncthreads();
        sh[t] += x;
        __syncthreads();
    }
    int incl = sh[t];
    int run = incl - s;
    if (t == 255) g_bsum[blockIdx.x] = incl;
#pragma unroll
    for (int j = 0; j < 4; j++) {
        int idx = base + j;
        if (idx < NRSEG) g_off[idx] = run;
        run += v[j];
    }
}

__global__ void scan2_kernel() {
    __shared__ int sh[512];
    int t = threadIdx.x;
    int v = (t < NSCAN_BLOCKS) ? g_bsum[t] : 0;
    sh[t] = v;
    __syncthreads();
    for (int off = 1; off < 512; off <<= 1) {
        int x = (t >= off) ? sh[t - off] : 0;
        __syncthreads();
        sh[t] += x;
        __syncthreads();
    }
    if (t < NSCAN_BLOCKS) g_bscan[t] = sh[t] - v;
    if (t == NSCAN_BLOCKS - 1) g_off[NRSEG] = sh[t];
}

__global__ void scan3_kernel() {
    int i = blockIdx.x * blockDim.x + threadIdx.x;
    if (i >= NRSEG) return;
    int v = g_off[i] + g_bscan[i / SCAN_CHUNK];
    g_off[i] = v;
    g_cur[i] = v;
    g_deg[i] = 0;          // reset for the NEXT call (deterministic)
}

__global__ void fill_kernel(const int* __restrict__ src, const int* __restrict__ dst,
                            const int* __restrict__ et) {
    int e = blockIdx.x * blockDim.x + threadIdx.x;
    if (e >= NEDGES) return;
    int seg = dst[e] * NREL + et[e];
    int pos = atomicAdd(&g_cur[seg], 1);
    g_esrc[pos] = src[e];
}

// ---------------------------------------------------------------------------
// Merged weight prep (R15 proven): one launch, heterogeneous blocks
// ---------------------------------------------------------------------------
#define W1_BLOCKS 288
#define WPREP_GRID (W1_BLOCKS + KDIM + CDIM)   // 1568

__global__ __launch_bounds__(128)
void weights_kernel(const float* __restrict__ W1, const float* __restrict__ root1,
                    const float* __restrict__ W2, const float* __restrict__ root2,
                    const float* __restrict__ linW,
                    const float* __restrict__ b2in, const float* __restrict__ linb) {
    int b = blockIdx.x;
    int t = threadIdx.x;

    if (b < W1_BLOCKS) {
        int i4 = b * 128 + t;
        const int cut4 = NREL * CDIM * CDIM / 4;
        float4 v = (i4 < cut4)
                 ? reinterpret_cast<const float4*>(W1)[i4]
                 : reinterpret_cast<const float4*>(root1)[i4 - cut4];
        v.x = tf32rf(v.x); v.y = tf32rf(v.y); v.z = tf32rf(v.z); v.w = tf32rf(v.w);
        reinterpret_cast<float4*>(g_w1)[i4] = v;
    } else if (b < W1_BLOCKS + KDIM) {
        __shared__ float rs[CDIM];
        int k = b - W1_BLOCKS;
        const float* row = (k < NREL * CDIM) ? (W2 + (size_t)k * CDIM)
                                             : (root2 + (size_t)(k - NREL * CDIM) * CDIM);
        rs[t] = row[t];
        __syncthreads();
        float s = 0.f;
#pragma unroll 8
        for (int c = 0; c < CDIM; c++) s += rs[c] * linW[c * CDIM + t];
        g_w2[(size_t)k * CDIM + t] = tf32rf(s);
    } else {
        __shared__ float red[CDIM];
        int j = b - W1_BLOCKS - KDIM;
        red[t] = b2in[t] * linW[t * CDIM + j];
        __syncthreads();
        for (int off = 64; off > 0; off >>= 1) {
            if (t < off) red[t] += red[t + off];
            __syncthreads();
        }
        if (t == 0) g_b2[j] = linb[j] + red[0];
    }
}

// ---------------------------------------------------------------------------
// Warp-specialized fused layer kernel.
//   smem: As[2][128][132] (A-tile double buffer, 135.2 KB)
//         Bs[2][16][132]  (B chunk double buffer,  16.9 KB)
// ---------------------------------------------------------------------------
#define AS_STRIDE 132
#define AS_FLOATS (128 * AS_STRIDE)          // 16896
#define BS_STRIDE 132
#define BS_FLOATS (16 * BS_STRIDE)           // 2112
#define FUSED_SMEM ((2 * AS_FLOATS + 2 * BS_FLOATS) * 4)   // 152064 bytes

template <int RELU>
__global__ __launch_bounds__(512, 1)
void fused_kernel(const float* __restrict__ feat, const float* __restrict__ B,
                  const float* __restrict__ bias, float* __restrict__ C) {
    extern __shared__ float sm[];
    float* As = sm;                       // [2][128][AS_STRIDE]
    float* Bs = sm + 2 * AS_FLOATS;       // [2][16][BS_STRIDE]

    const int tid  = threadIdx.x;
    const int warp = tid >> 5;
    const int lane = tid & 31;
    const int blockRow = blockIdx.x * 128;
    const float4* f4 = reinterpret_cast<const float4*>(feat);

    if (warp < 8) {
        // ================= MMA consumers (256 threads) =================
        const int wm = (warp & 1) * 64;
        const int wn = (warp >> 1) * 32;
        const int gid = lane >> 2;
        const int tg  = lane & 3;

        float acc[4][4][4];
#pragma unroll
        for (int a = 0; a < 4; a++)
#pragma unroll
            for (int b = 0; b < 4; b++)
#pragma unroll
                for (int c = 0; c < 4; c++) acc[a][b][c] = 0.f;

        const int br = warp;              // 0..7 (tid<256)
        const int bc = lane * 4;

        auto stageB = [&](int g) {
            float* d = Bs + (g & 1) * BS_FLOATS;
            cpa16(&d[br * BS_STRIDE + bc],       B + (size_t)(g * 16 + br) * CDIM + bc, true);
            cpa16(&d[(br + 8) * BS_STRIDE + bc], B + (size_t)(g * 16 + br + 8) * CDIM + bc, true);
            asm volatile("cp.async.commit_group;");
        };

        stageB(0);
        constexpr int NG = KDIM / 16;     // 72
#pragma unroll 1
        for (int g = 0; g < NG; g++) {
            int r = g >> 3;
            int c = g & 7;
            if (c == 0) bar_sync(BAR_FULL0 + (r & 1), 512);     // A tile r ready
            if (g + 1 < NG) {
                stageB(g + 1);
                asm volatile("cp.async.wait_group 1;");
            } else {
                asm volatile("cp.async.wait_group 0;");
            }
            bar_sync(BAR_MMA_A, 256);     // Bs[g&1] staged by all MMA warps

            const float* as = As + (r & 1) * AS_FLOATS;
            const float* bs = Bs + (g & 1) * BS_FLOATS;
            const int cb = c * 16;
#pragma unroll
            for (int ks = 0; ks < 16; ks += 8) {
                uint32_t af[4][4], bf[4][2];
#pragma unroll
                for (int mi = 0; mi < 4; mi++) {
                    int rr = wm + mi * 16 + gid;
                    af[mi][0] = __float_as_uint(as[rr * AS_STRIDE + cb + ks + tg]);
                    af[mi][1] = __float_as_uint(as[(rr + 8) * AS_STRIDE + cb + ks + tg]);
                    af[mi][2] = __float_as_uint(as[rr * AS_STRIDE + cb + ks + tg + 4]);
                    af[mi][3] = __float_as_uint(as[(rr + 8) * AS_STRIDE + cb + ks + tg + 4]);
                }
#pragma unroll
                for (int ni = 0; ni < 4; ni++) {
                    int n = wn + ni * 8 + gid;
                    bf[ni][0] = __float_as_uint(bs[(ks + tg) * BS_STRIDE + n]);
                    bf[ni][1] = __float_as_uint(bs[(ks + tg + 4) * BS_STRIDE + n]);
                }
#pragma unroll
                for (int mi = 0; mi < 4; mi++)
#pragma unroll
                    for (int ni = 0; ni < 4; ni++) mma8(acc[mi][ni], af[mi], bf[ni]);
            }
            bar_sync(BAR_MMA_B, 256);     // all MMA warps done reading Bs[g&1]
            if (c == 7 && r < 7) bar_arrive(BAR_FREE0 + (r & 1), 512);  // A tile consumed
        }

        // epilogue: bias (+relu), guarded float2 stores
#pragma unroll
        for (int mi = 0; mi < 4; mi++) {
            int r0 = blockRow + wm + mi * 16 + gid;
            int r1 = r0 + 8;
#pragma unroll
            for (int ni = 0; ni < 4; ni++) {
                int col = wn + ni * 8 + tg * 2;
                float b0 = bias[col], b1 = bias[col + 1];
                float v0 = acc[mi][ni][0] + b0;
                float v1 = acc[mi][ni][1] + b1;
                float v2 = acc[mi][ni][2] + b0;
                float v3 = acc[mi][ni][3] + b1;
                if (RELU) {
                    v0 = fmaxf(v0, 0.f); v1 = fmaxf(v1, 0.f);
                    v2 = fmaxf(v2, 0.f); v3 = fmaxf(v3, 0.f);
                }
                if (r0 < NNODES) {
                    float2 t; t.x = v0; t.y = v1;
                    *reinterpret_cast<float2*>(C + (size_t)r0 * CDIM + col) = t;
                }
                if (r1 < NNODES) {
                    float2 t; t.x = v2; t.y = v3;
                    *reinterpret_cast<float2*>(C + (size_t)r1 * CDIM + col) = t;
                }
            }
        }
    } else {
        // ================= gather producers (256 threads) =================
        const int pw = warp - 8;          // 0..7, owns rows pw*16 .. pw*16+15
#pragma unroll 1
        for (int r = 0; r < NREL + 1; r++) {
            if (r >= 2) bar_sync(BAR_FREE0 + (r & 1), 512);     // buffer recycled
            float* At = As + (r & 1) * AS_FLOATS;

            if (r < NREL) {
                // segment-mean gather, two rows interleaved for MLP
#pragma unroll 1
                for (int i = 0; i < 16; i += 2) {
                    int row0 = pw * 16 + i;
                    int n0 = blockRow + row0;
                    int n1 = n0 + 1;
                    float4 a0 = make_float4(0.f, 0.f, 0.f, 0.f);
                    float4 a1 = make_float4(0.f, 0.f, 0.f, 0.f);
                    int b0 = 0, e0 = 0, b1 = 0, e1 = 0;
                    if (n0 < NNODES) {
                        int sg = n0 * NREL + r;
                        b0 = __ldg(&g_off[sg]); e0 = __ldg(&g_off[sg + 1]);
                    }
                    if (n1 < NNODES) {
                        int sg = n1 * NREL + r;
                        b1 = __ldg(&g_off[sg]); e1 = __ldg(&g_off[sg + 1]);
                    }
                    int i0 = b0, i1 = b1;
                    // paired phase (MLP 2)
                    while (i0 < e0 && i1 < e1) {
                        int s0 = __ldg(&g_esrc[i0]);
                        int s1 = __ldg(&g_esrc[i1]);
                        float4 v0 = f4[(size_t)s0 * 32 + lane];
                        float4 v1 = f4[(size_t)s1 * 32 + lane];
                        a0.x += v0.x; a0.y += v0.y; a0.z += v0.z; a0.w += v0.w;
                        a1.x += v1.x; a1.y += v1.y; a1.z += v1.z; a1.w += v1.w;
                        i0++; i1++;
                    }
                    // drain row0 (MLP 2)
                    while (i0 + 2 <= e0) {
                        int s0 = __ldg(&g_esrc[i0]);
                        int s1 = __ldg(&g_esrc[i0 + 1]);
                        float4 v0 = f4[(size_t)s0 * 32 + lane];
                        float4 v1 = f4[(size_t)s1 * 32 + lane];
                        a0.x += v0.x; a0.y += v0.y; a0.z += v0.z; a0.w += v0.w;
                        a0.x += v1.x; a0.y += v1.y; a0.z += v1.z; a0.w += v1.w;
                        i0 += 2;
                    }
                    if (i0 < e0) {
                        int s0 = __ldg(&g_esrc[i0]);
                        float4 v0 = f4[(size_t)s0 * 32 + lane];
                        a0.x += v0.x; a0.y += v0.y; a0.z += v0.z; a0.w += v0.w;
                    }
                    // drain row1 (MLP 2)
                    while (i1 + 2 <= e1) {
                        int s0 = __ldg(&g_esrc[i1]);
                        int s1 = __ldg(&g_esrc[i1 + 1]);
                        float4 v0 = f4[(size_t)s0 * 32 + lane];
                        float4 v1 = f4[(size_t)s1 * 32 + lane];
                        a1.x += v0.x; a1.y += v0.y; a1.z += v0.z; a1.w += v0.w;
                        a1.x += v1.x; a1.y += v1.y; a1.z += v1.z; a1.w += v1.w;
                        i1 += 2;
                    }
                    if (i1 < e1) {
                        int s0 = __ldg(&g_esrc[i1]);
                        float4 v0 = f4[(size_t)s0 * 32 + lane];
                        a1.x += v0.x; a1.y += v0.y; a1.z += v0.z; a1.w += v0.w;
                    }
                    float inv0 = (e0 > b0) ? 1.0f / (float)(e0 - b0) : 0.0f;
                    float inv1 = (e1 > b1) ? 1.0f / (float)(e1 - b1) : 0.0f;
                    a0.x = tf32rf(a0.x * inv0); a0.y = tf32rf(a0.y * inv0);
                    a0.z = tf32rf(a0.z * inv0); a0.w = tf32rf(a0.w * inv0);
                    a1.x = tf32rf(a1.x * inv1); a1.y = tf32rf(a1.y * inv1);
                    a1.z = tf32rf(a1.z * inv1); a1.w = tf32rf(a1.w * inv1);
                    *reinterpret_cast<float4*>(&At[row0 * AS_STRIDE + lane * 4]) = a0;
                    *reinterpret_cast<float4*>(&At[(row0 + 1) * AS_STRIDE + lane * 4]) = a1;
                }
            } else {
                // root tile: rounded copy of the node's own feature row
#pragma unroll 1
                for (int i = 0; i < 16; i++) {
                    int row = pw * 16 + i;
                    int n = blockRow + row;
                    float4 v = make_float4(0.f, 0.f, 0.f, 0.f);
                    if (n < NNODES) v = f4[(size_t)n * 32 + lane];
                    v.x = tf32rf(v.x); v.y = tf32rf(v.y);
                    v.z = tf32rf(v.z); v.w = tf32rf(v.w);
                    *reinterpret_cast<float4*>(&At[row * AS_STRIDE + lane * 4]) = v;
                }
            }
            bar_arrive(BAR_FULL0 + (r & 1), 512);               // A tile r ready
        }
    }
}

// ---------------------------------------------------------------------------
extern "C" void kernel_launch(void* const* d_in, const int* in_sizes, int n_in,
                              void* d_out, int out_size) {
    const float* x     = (const float*)d_in[0];
    const int*   ei    = (const int*)  d_in[1];
    const int*   et    = (const int*)  d_in[2];
    const float* W1    = (const float*)d_in[3];
    const float* root1 = (const float*)d_in[4];
    const float* b1    = (const float*)d_in[5];
    const float* W2    = (const float*)d_in[6];
    const float* root2 = (const float*)d_in[7];
    const float* b2    = (const float*)d_in[8];
    const float* linW  = (const float*)d_in[9];
    const float* linb  = (const float*)d_in[10];
    float* out = (float*)d_out;

    const int* src = ei;
    const int* dst = ei + NEDGES;

    float *p_h, *p_w1, *p_w2, *p_b2;
    cudaGetSymbolAddress((void**)&p_h,  g_h);
    cudaGetSymbolAddress((void**)&p_w1, g_w1);
    cudaGetSymbolAddress((void**)&p_w2, g_w2);
    cudaGetSymbolAddress((void**)&p_b2, g_b2);

    // >48KB dynamic smem for the fused kernels (host-side attr; capture-safe)
    cudaFuncSetAttribute(fused_kernel<1>,
                         cudaFuncAttributeMaxDynamicSharedMemorySize, FUSED_SMEM);
    cudaFuncSetAttribute(fused_kernel<0>,
                         cudaFuncAttributeMaxDynamicSharedMemorySize, FUSED_SMEM);

    // CSR build (g_deg zeroed at module load / by previous call's scan3)
    hist_kernel<<<(NEDGES + 255) / 256, 256>>>(dst, et);
    scan1_kernel<<<NSCAN_BLOCKS, 256>>>();
    scan2_kernel<<<1, 512>>>();
    scan3_kernel<<<(NRSEG + 255) / 256, 256>>>();
    fill_kernel<<<(NEDGES + 255) / 256, 256>>>(src, dst, et);

    // merged weight prep
    weights_kernel<<<WPREP_GRID, 128>>>(W1, root1, W2, root2, linW, b2, linb);

    const int nblk = (NNODES + 127) / 128;   // 391

    // layer 1 (relu), fused aggregate+GEMM
    fused_kernel<1><<<nblk, 512, FUSED_SMEM>>>(x, p_w1, b1, p_h);
    // layer 2 (final linear folded into weights)
    fused_kernel<0><<<nblk, 512, FUSED_SMEM>>>(p_h, p_w2, p_b2, out);
}